// round 12
// baseline (speedup 1.0000x reference)
#include <cuda_runtime.h>
#include <cstdint>
#include <mma.h>

using namespace nvcuda;

#define DMODEL 1024
#define NH     16
#define DH     64
#define BATCH  4
#define SEQ    1024
#define JT     32            // j chunk
#define NC     (SEQ/JT)      // 32 chunks
#define IT2    2             // i per CTA

// Scratch (static device globals)
__device__ float g_q  [(size_t)BATCH*SEQ*DMODEL];   // [b, i, h*64+d]
__device__ float g_k  [(size_t)BATCH*SEQ*DH];       // [b, j, d]
__device__ float g_v  [(size_t)BATCH*SEQ*DH];       // [b, j, d]
__device__ float g_ctx[(size_t)BATCH*SEQ*DMODEL];   // [b, i, h*64+d]

// ---------------------------------------------------------------------------
__device__ __forceinline__ void cp16(void* dst, const void* src) {
    unsigned d = (unsigned)__cvta_generic_to_shared(dst);
    asm volatile("cp.async.cg.shared.global [%0], [%1], 16;" :: "r"(d), "l"(src));
}
__device__ __forceinline__ void cp_commit() { asm volatile("cp.async.commit_group;"); }
template<int N> __device__ __forceinline__ void cp_wait() {
    asm volatile("cp.async.wait_group %0;" :: "n"(N));
}
// In-place tf32 RN rounding of 4 floats in smem
__device__ __forceinline__ void cvt4(float* p) {
    float4 v = *reinterpret_cast<float4*>(p);
    v.x = wmma::__float_to_tf32(v.x);
    v.y = wmma::__float_to_tf32(v.y);
    v.z = wmma::__float_to_tf32(v.z);
    v.w = wmma::__float_to_tf32(v.w);
    *reinterpret_cast<float4*>(p) = v;
}

// ===========================================================================
// Fused attention: CTA = 2 i values, 512 threads (16 warps), j-loop of 32
// chunks, double-buffered cp.async staging.  P never touches gmem.
// Tiles are tf32-rounded IN SMEM once per chunk; fragment loads are raw.
// ===========================================================================
struct FBuf  { float R[IT2][JT][68]; float K[4][JT][68]; float V[4][JT][68]; };
struct FSmem {
    float Qs[IT2][64][68];
    FBuf  buf[2];
    float Ps[128][36];
    float lsum[128];
};
#define FUSED_SMEM ((int)sizeof(FSmem))

__global__ void __launch_bounds__(512, 1)
fused_attn_kernel(const float* __restrict__ rel)
{
    extern __shared__ float smraw[];
    FSmem* sm = reinterpret_cast<FSmem*>(smraw);

    const int tid  = threadIdx.x;
    const int warp = tid >> 5;
    const int rb   = warp >> 1;          // 16-row block: il = rb>>2, b = rb&3
    const int wil  = rb >> 2;
    const int wb   = rb & 3;
    const int wh   = warp & 1;           // j-half (S phase) / d-half (AV phase)
    const int i0   = blockIdx.x * IT2;

    // ---- staging helper for one j chunk into buf[pb]
    auto stage = [&](int pb, int j0) {
        FBuf& B = sm->buf[pb];
        #pragma unroll
        for (int t = 0; t < 2; ++t) {                 // rel: 1024 float4
            int idx = tid + t*512;
            int il  = idx >> 9;
            int j   = (idx >> 4) & 31;
            int c4  = (idx & 15) * 4;
            cp16(&B.R[il][j][c4],
                 rel + ((size_t)(i0 + il)*SEQ + j0 + j)*DH + c4);
        }
        #pragma unroll
        for (int t = 0; t < 4; ++t) {                 // K: 2048 float4
            int idx = tid + t*512;
            int b   = idx >> 9;
            int j   = (idx >> 4) & 31;
            int c4  = (idx & 15) * 4;
            cp16(&B.K[b][j][c4], g_k + ((size_t)b*SEQ + j0 + j)*DH + c4);
        }
        #pragma unroll
        for (int t = 0; t < 4; ++t) {                 // V: 2048 float4
            int idx = tid + t*512;
            int b   = idx >> 9;
            int j   = (idx >> 4) & 31;
            int c4  = (idx & 15) * 4;
            cp16(&B.V[b][j][c4], g_v + ((size_t)b*SEQ + j0 + j)*DH + c4);
        }
        cp_commit();
    };

    // ---- prologue: Q rows (both i), lsum zero, first chunk
    #pragma unroll
    for (int t = 0; t < 4; ++t) {                     // Q: 2048 float4
        int idx = tid + t*512;
        int il  = idx >> 10;
        int r   = (idx >> 4) & 63;
        int c4  = (idx & 15) * 4;
        int b = r >> 4, h = r & 15;
        cp16(&sm->Qs[il][r][c4],
             g_q + ((size_t)(b*SEQ + i0 + il))*DMODEL + h*DH + c4);
    }
    if (tid < 128) sm->lsum[tid] = 0.0f;
    stage(0, 0);

    // O accumulator: warp owns rows [rb*16, +16), cols [wh*32, +32)
    wmma::fragment<wmma::accumulator, 16, 16, 8, float> of[2];
    wmma::fill_fragment(of[0], 0.0f);
    wmma::fill_fragment(of[1], 0.0f);

    for (int c = 0; c < NC; ++c) {
        const int pb = c & 1;
        cp_wait<0>();
        __syncthreads();                  // buf[pb] landed; prev AV complete

        if (c + 1 < NC) stage(pb ^ 1, (c + 1)*JT);

        FBuf& B = sm->buf[pb];

        // ---- in-place tf32 rounding of this chunk's tiles (+Q on chunk 0)
        if (c == 0) {
            #pragma unroll
            for (int t = 0; t < 4; ++t) {
                int idx = tid + t*512;
                cvt4(&sm->Qs[idx >> 10][(idx >> 4) & 63][(idx & 15)*4]);
            }
        }
        #pragma unroll
        for (int t = 0; t < 2; ++t) {
            int idx = tid + t*512;
            cvt4(&B.R[idx >> 9][(idx >> 4) & 31][(idx & 15)*4]);
        }
        #pragma unroll
        for (int t = 0; t < 4; ++t) {
            int idx = tid + t*512;
            cvt4(&B.K[idx >> 9][(idx >> 4) & 31][(idx & 15)*4]);
        }
        #pragma unroll
        for (int t = 0; t < 4; ++t) {
            int idx = tid + t*512;
            cvt4(&B.V[idx >> 9][(idx >> 4) & 31][(idx & 15)*4]);
        }
        __syncthreads();                  // rounded tiles visible

        // ---- S = Q·K^T + Q·R^T  (warp: 16 rows x 16 j)
        wmma::fragment<wmma::accumulator, 16, 16, 8, float> sf;
        wmma::fill_fragment(sf, 0.0f);
        #pragma unroll
        for (int kf = 0; kf < 8; ++kf) {
            wmma::fragment<wmma::matrix_a, 16, 16, 8, wmma::precision::tf32, wmma::row_major> af;
            wmma::fragment<wmma::matrix_b, 16, 16, 8, wmma::precision::tf32, wmma::col_major> bk, br;
            wmma::load_matrix_sync(af, &sm->Qs[wil][wb*16][kf*8], 68);
            wmma::load_matrix_sync(bk, &B.K[wb][wh*16][kf*8], 68);
            wmma::mma_sync(sf, af, bk, sf);
            wmma::load_matrix_sync(br, &B.R[wil][wh*16][kf*8], 68);
            wmma::mma_sync(sf, af, br, sf);
        }
        #pragma unroll
        for (int t = 0; t < sf.num_elements; ++t)
            sf.x[t] = wmma::__float_to_tf32(__expf(sf.x[t] * 0.125f));
        wmma::store_matrix_sync(&sm->Ps[rb*16][wh*16], sf, 36, wmma::mem_row_major);
        __syncthreads();                  // Ps complete

        // ---- row sums (4 threads/row, 8 cols each)
        {
            int r = tid >> 2;
            int q = tid & 3;
            float s = 0.0f;
            #pragma unroll
            for (int cc = 0; cc < 8; ++cc) s += sm->Ps[r][q*8 + cc];
            s += __shfl_xor_sync(0xffffffffu, s, 1);
            s += __shfl_xor_sync(0xffffffffu, s, 2);
            if (q == 0) sm->lsum[r] += s;
        }

        // ---- O += P · V   (warp: 16 rows x 32 d)
        #pragma unroll
        for (int kf = 0; kf < 4; ++kf) {
            wmma::fragment<wmma::matrix_a, 16, 16, 8, wmma::precision::tf32, wmma::row_major> af;
            wmma::load_matrix_sync(af, &sm->Ps[rb*16][kf*8], 36);
            #pragma unroll
            for (int nf = 0; nf < 2; ++nf) {
                wmma::fragment<wmma::matrix_b, 16, 16, 8, wmma::precision::tf32, wmma::row_major> bf;
                wmma::load_matrix_sync(bf, &B.V[wb][kf*8][wh*32 + nf*16], 68);
                wmma::mma_sync(of[nf], af, bf, of[nf]);
            }
        }
    }

    // ---- epilogue: stage O into smem (reuse buf[0]), divide by lsum, write
    __syncthreads();
    float (*Os)[68] = reinterpret_cast<float (*)[68]>(&sm->buf[0].R[0][0][0]);
    #pragma unroll
    for (int nf = 0; nf < 2; ++nf)
        wmma::store_matrix_sync(&Os[rb*16][wh*32 + nf*16], of[nf], 68,
                                wmma::mem_row_major);
    __syncthreads();

    #pragma unroll
    for (int t = 0; t < 4; ++t) {                     // 2048 float4
        int idx = tid + t*512;
        int r   = idx >> 4;            // 0..127
        int c4  = (idx & 15) * 4;
        int il  = r >> 6;
        int rr  = r & 63;
        int b = rr >> 4, h = rr & 15;
        float inv = 1.0f / sm->lsum[r];
        float4 o;
        o.x = Os[r][c4+0] * inv;
        o.y = Os[r][c4+1] * inv;
        o.z = Os[r][c4+2] * inv;
        o.w = Os[r][c4+3] * inv;
        *reinterpret_cast<float4*>(
            g_ctx + ((size_t)(b*SEQ + i0 + il))*DMODEL + h*DH + c4) = o;
    }
}

// ===========================================================================
// 128x128 NT GEMM (C = A·B^T), cp.async double-buffered, 8 warps (warp 32x64)
// Smem tiles tf32-rounded in place per k-step; fragment loads raw.
// ===========================================================================
struct ProjSmem { float A[2][128][36]; float B[2][128][36]; };
#define PROJ_SMEM ((int)sizeof(ProjSmem))

__global__ void __launch_bounds__(256, 2)
gemm_nt_128p(const float* __restrict__ A, int lda,
             const float* __restrict__ B, int ldb,
             float* __restrict__ C, int ldc, int K)
{
    extern __shared__ float smraw[];
    ProjSmem* sm = reinterpret_cast<ProjSmem*>(smraw);

    const int tid  = threadIdx.x;
    const int warp = tid >> 5;
    const int wm   = warp >> 1;      // 0..3
    const int wn   = warp & 1;       // 0..1

    A += (size_t)blockIdx.x * 128 * lda;
    B += (size_t)blockIdx.y * 128 * ldb;
    C += (size_t)blockIdx.x * 128 * ldc + (size_t)blockIdx.y * 128;

    auto stage = [&](int buf, int k0) {
        #pragma unroll
        for (int t = 0; t < 4; ++t) {
            int idx = tid + t*256;           // 0..1023
            int r   = idx >> 3;              // 0..127
            int c4  = (idx & 7) * 4;         // 0..28
            cp16(&sm->A[buf][r][c4], A + (size_t)r*lda + k0 + c4);
            cp16(&sm->B[buf][r][c4], B + (size_t)r*ldb + k0 + c4);
        }
        cp_commit();
    };

    wmma::fragment<wmma::accumulator, 16, 16, 8, float> cf[2][4];
    #pragma unroll
    for (int mi = 0; mi < 2; ++mi)
        #pragma unroll
        for (int ni = 0; ni < 4; ++ni) wmma::fill_fragment(cf[mi][ni], 0.0f);

    stage(0, 0);
    int cur = 0;
    for (int k0 = 0; k0 < K; k0 += 32) {
        if (k0 + 32 < K) { stage(cur ^ 1, k0 + 32); cp_wait<1>(); }
        else             { cp_wait<0>(); }
        __syncthreads();

        // in-place tf32 rounding of buf[cur]
        #pragma unroll
        for (int t = 0; t < 4; ++t) {
            int idx = tid + t*256;
            cvt4(&sm->A[cur][idx >> 3][(idx & 7)*4]);
            cvt4(&sm->B[cur][idx >> 3][(idx & 7)*4]);
        }
        __syncthreads();

        #pragma unroll
        for (int kf = 0; kf < 4; ++kf) {
            wmma::fragment<wmma::matrix_a, 16, 16, 8, wmma::precision::tf32, wmma::row_major> af[2];
            wmma::fragment<wmma::matrix_b, 16, 16, 8, wmma::precision::tf32, wmma::col_major> bf[4];
            #pragma unroll
            for (int mi = 0; mi < 2; ++mi)
                wmma::load_matrix_sync(af[mi], &sm->A[cur][wm*32 + mi*16][kf*8], 36);
            #pragma unroll
            for (int ni = 0; ni < 4; ++ni)
                wmma::load_matrix_sync(bf[ni], &sm->B[cur][wn*64 + ni*16][kf*8], 36);
            #pragma unroll
            for (int mi = 0; mi < 2; ++mi)
                #pragma unroll
                for (int ni = 0; ni < 4; ++ni)
                    wmma::mma_sync(cf[mi][ni], af[mi], bf[ni], cf[mi][ni]);
        }
        __syncthreads();
        cur ^= 1;
    }

    #pragma unroll
    for (int mi = 0; mi < 2; ++mi)
        #pragma unroll
        for (int ni = 0; ni < 4; ++ni)
            wmma::store_matrix_sync(
                C + (size_t)(wm*32 + mi*16)*ldc + (wn*64 + ni*16),
                cf[mi][ni], ldc, wmma::mem_row_major);
}

// ===========================================================================
// Combined K/V projection: one 128-wide NT GEMM over stacked [Wk; Wv].
// x is read once.  Columns 0..63 -> g_k, 64..127 -> g_v (both ld=64).
// ===========================================================================
__global__ void __launch_bounds__(256, 2)
kv_proj_kernel(const float* __restrict__ x,
               const float* __restrict__ Wk,
               const float* __restrict__ Wv)
{
    extern __shared__ float smraw[];
    ProjSmem* sm = reinterpret_cast<ProjSmem*>(smraw);

    const int tid  = threadIdx.x;
    const int warp = tid >> 5;
    const int wm   = warp >> 1;      // 0..3
    const int wn   = warp & 1;       // 0..1 (0 -> K, 1 -> V)

    const float* Ax = x + (size_t)blockIdx.x * 128 * DMODEL;

    auto stage = [&](int buf, int k0) {
        #pragma unroll
        for (int t = 0; t < 4; ++t) {
            int idx = tid + t*256;
            int r   = idx >> 3;
            int c4  = (idx & 7) * 4;
            cp16(&sm->A[buf][r][c4], Ax + (size_t)r*DMODEL + k0 + c4);
            const float* src = (r < 64) ? (Wk + (size_t)r*DMODEL)
                                        : (Wv + (size_t)(r - 64)*DMODEL);
            cp16(&sm->B[buf][r][c4], src + k0 + c4);
        }
        cp_commit();
    };

    wmma::fragment<wmma::accumulator, 16, 16, 8, float> cf[2][4];
    #pragma unroll
    for (int mi = 0; mi < 2; ++mi)
        #pragma unroll
        for (int ni = 0; ni < 4; ++ni) wmma::fill_fragment(cf[mi][ni], 0.0f);

    stage(0, 0);
    int cur = 0;
    for (int k0 = 0; k0 < DMODEL; k0 += 32) {
        if (k0 + 32 < DMODEL) { stage(cur ^ 1, k0 + 32); cp_wait<1>(); }
        else                  { cp_wait<0>(); }
        __syncthreads();

        #pragma unroll
        for (int t = 0; t < 4; ++t) {
            int idx = tid + t*256;
            cvt4(&sm->A[cur][idx >> 3][(idx & 7)*4]);
            cvt4(&sm->B[cur][idx >> 3][(idx & 7)*4]);
        }
        __syncthreads();

        #pragma unroll
        for (int kf = 0; kf < 4; ++kf) {
            wmma::fragment<wmma::matrix_a, 16, 16, 8, wmma::precision::tf32, wmma::row_major> af[2];
            wmma::fragment<wmma::matrix_b, 16, 16, 8, wmma::precision::tf32, wmma::col_major> bf[4];
            #pragma unroll
            for (int mi = 0; mi < 2; ++mi)
                wmma::load_matrix_sync(af[mi], &sm->A[cur][wm*32 + mi*16][kf*8], 36);
            #pragma unroll
            for (int ni = 0; ni < 4; ++ni)
                wmma::load_matrix_sync(bf[ni], &sm->B[cur][wn*64 + ni*16][kf*8], 36);
            #pragma unroll
            for (int mi = 0; mi < 2; ++mi)
                #pragma unroll
                for (int ni = 0; ni < 4; ++ni)
                    wmma::mma_sync(cf[mi][ni], af[mi], bf[ni], cf[mi][ni]);
        }
        __syncthreads();
        cur ^= 1;
    }

    float* Ct = (wn == 0) ? g_k : g_v;
    Ct += ((size_t)blockIdx.x * 128 + wm*32) * DH;
    #pragma unroll
    for (int mi = 0; mi < 2; ++mi)
        #pragma unroll
        for (int ni = 0; ni < 4; ++ni)
            wmma::store_matrix_sync(
                Ct + (size_t)(mi*16)*DH + ni*16,
                cf[mi][ni], DH, wmma::mem_row_major);
}

// ---------------------------------------------------------------------------
__global__ void bias_add(float* __restrict__ out, const float* __restrict__ bo)
{
    size_t idx = (size_t)blockIdx.x * 256 + threadIdx.x;
    out[idx] += bo[idx & (DMODEL - 1)];
}

// ---------------------------------------------------------------------------
extern "C" void kernel_launch(void* const* d_in, const int* in_sizes, int n_in,
                              void* d_out, int out_size)
{
    const float* x   = (const float*)d_in[0];
    const float* rel = (const float*)d_in[1];
    const float* Wq  = (const float*)d_in[2];
    const float* Wk  = (const float*)d_in[3];
    const float* Wv  = (const float*)d_in[4];
    const float* Wo  = (const float*)d_in[5];
    const float* bo  = (const float*)d_in[6];
    float* out = (float*)d_out;

    float *q, *ctx;
    cudaGetSymbolAddress((void**)&q,   g_q);
    cudaGetSymbolAddress((void**)&ctx, g_ctx);

    cudaFuncSetAttribute(gemm_nt_128p, cudaFuncAttributeMaxDynamicSharedMemorySize, PROJ_SMEM);
    cudaFuncSetAttribute(kv_proj_kernel, cudaFuncAttributeMaxDynamicSharedMemorySize, PROJ_SMEM);
    cudaFuncSetAttribute(fused_attn_kernel, cudaFuncAttributeMaxDynamicSharedMemorySize, FUSED_SMEM);

    // Projections: y = x @ W^T
    gemm_nt_128p<<<dim3(32, 8), 256, PROJ_SMEM>>>(x, DMODEL, Wq, DMODEL, q, DMODEL, DMODEL);
    kv_proj_kernel<<<32, 256, PROJ_SMEM>>>(x, Wk, Wv);

    // Fused c2c + c2p + softmax + AV (P never hits gmem)
    fused_attn_kernel<<<SEQ/IT2, 512, FUSED_SMEM>>>(rel);

    // out = ctx @ Wo^T + bo
    gemm_nt_128p<<<dim3(32, 8), 256, PROJ_SMEM>>>(ctx, DMODEL, Wo, DMODEL, out, DMODEL, DMODEL);
    bias_add<<<16384, 256>>>(out, bo);
}

// round 13
// speedup vs baseline: 1.8869x; 1.8869x over previous
#include <cuda_runtime.h>
#include <cstdint>
#include <mma.h>

using namespace nvcuda;

#define DMODEL 1024
#define NH     16
#define DH     64
#define BATCH  4
#define SEQ    1024
#define JC2    64

// Scratch (static device globals)
__device__ float g_q  [(size_t)BATCH*SEQ*DMODEL];   // [b, i, h*64+d]  (tf32-rounded)
__device__ float g_k  [(size_t)BATCH*SEQ*DH];       // [b, j, d]       (tf32-rounded)
__device__ float g_v  [(size_t)BATCH*SEQ*DH];       // [b, j, d]       (tf32-rounded)
__device__ float g_p  [(size_t)64*SEQ*SEQ];         // [b][i][h][j]    (tf32-rounded)
__device__ float g_l  [(size_t)BATCH*SEQ*NH];       // row sums
__device__ float g_ctx[(size_t)BATCH*SEQ*DMODEL];   // [b, i, h*64+d]

// ---------------------------------------------------------------------------
__device__ __forceinline__ void cp16(void* dst, const void* src) {
    unsigned d = (unsigned)__cvta_generic_to_shared(dst);
    asm volatile("cp.async.cg.shared.global [%0], [%1], 16;" :: "r"(d), "l"(src));
}
__device__ __forceinline__ void cp_commit() { asm volatile("cp.async.commit_group;"); }
template<int N> __device__ __forceinline__ void cp_wait() {
    asm volatile("cp.async.wait_group %0;" :: "n"(N));
}
template<class F> __device__ __forceinline__ void to_tf32(F& f) {
    #pragma unroll
    for (int t = 0; t < f.num_elements; ++t)
        f.x[t] = wmma::__float_to_tf32(f.x[t]);
}

// ===========================================================================
// c2cp: P[b,i,h,j] = exp(q·(k+rel)/8)  — c2p folded into c2c via the identity
// q·k + q·rel = q·(k+rel).  One-shot CTA per (i, j-tile of 64), 256 threads.
// g_q/g_k are pre-rounded tf32; rel folded+rounded in smem; zero cvts in loop.
// ===========================================================================
struct C2PSmem {
    float Qs[64][68];        // rows (b,h), cols d
    float KR[4][JC2][68];    // [b][j][d] = k + rel  (KR[0] reused as P staging)
};
#define C2P_SMEM ((int)sizeof(C2PSmem))

__global__ void __launch_bounds__(256, 2)
c2cp_kernel(const float* __restrict__ rel)
{
    extern __shared__ float smraw[];
    C2PSmem* sm = reinterpret_cast<C2PSmem*>(smraw);

    const int tid  = threadIdx.x;
    const int warp = tid >> 5;
    const int wb   = warp >> 1;        // batch 0..3
    const int wn   = warp & 1;         // j half
    const int i    = blockIdx.x;
    const int j0   = blockIdx.y * JC2;

    // Stage Q (gathered rows) and K (all 4 batches) via cp.async
    #pragma unroll
    for (int t = 0; t < 4; ++t) {
        int idx = tid + t*256;          // 0..1023
        int r   = idx >> 4;             // 0..63
        int c4  = (idx & 15) * 4;
        cp16(&sm->Qs[r][c4],
             g_q + ((size_t)((r >> 4)*SEQ + i))*DMODEL + (r & 15)*DH + c4);
    }
    #pragma unroll
    for (int t = 0; t < 16; ++t) {
        int idx = tid + t*256;          // 0..4095
        int b   = idx >> 10;
        int j   = (idx >> 4) & 63;
        int c4  = (idx & 15) * 4;
        cp16(&sm->KR[b][j][c4], g_k + ((size_t)(b*SEQ + j0 + j))*DH + c4);
    }
    cp_commit();

    // rel loads overlap the cp.async wait (read once per CTA; once globally)
    float4 rv[4];
    #pragma unroll
    for (int t = 0; t < 4; ++t) {
        int idx = tid + t*256;
        int j   = idx >> 4;
        int c4  = (idx & 15) * 4;
        rv[t] = *reinterpret_cast<const float4*>(
            rel + ((size_t)i*SEQ + j0 + j)*DH + c4);
    }
    cp_wait<0>();
    __syncthreads();

    // Fold rel into all 4 batches' K, round to tf32
    #pragma unroll
    for (int t = 0; t < 4; ++t) {
        int idx = tid + t*256;
        int j   = idx >> 4;
        int c4  = (idx & 15) * 4;
        #pragma unroll
        for (int b = 0; b < 4; ++b) {
            float4 kr = *reinterpret_cast<float4*>(&sm->KR[b][j][c4]);
            kr.x = wmma::__float_to_tf32(kr.x + rv[t].x);
            kr.y = wmma::__float_to_tf32(kr.y + rv[t].y);
            kr.z = wmma::__float_to_tf32(kr.z + rv[t].z);
            kr.w = wmma::__float_to_tf32(kr.w + rv[t].w);
            *reinterpret_cast<float4*>(&sm->KR[b][j][c4]) = kr;
        }
    }
    __syncthreads();

    // S = Q·(K+R)^T   (warp: 16 h-rows x 32 j) — raw fragment loads, no cvts
    wmma::fragment<wmma::accumulator, 16, 16, 8, float> sf[2];
    wmma::fill_fragment(sf[0], 0.0f);
    wmma::fill_fragment(sf[1], 0.0f);
    #pragma unroll
    for (int kf = 0; kf < 8; ++kf) {
        wmma::fragment<wmma::matrix_a, 16, 16, 8, wmma::precision::tf32, wmma::row_major> af;
        wmma::load_matrix_sync(af, &sm->Qs[wb*16][kf*8], 68);
        #pragma unroll
        for (int ni = 0; ni < 2; ++ni) {
            wmma::fragment<wmma::matrix_b, 16, 16, 8, wmma::precision::tf32, wmma::col_major> bk;
            wmma::load_matrix_sync(bk, &sm->KR[wb][wn*32 + ni*16][kf*8], 68);
            wmma::mma_sync(sf[ni], af, bk, sf[ni]);
        }
    }
    // P = exp(S/8), rounded to tf32 once here (consumed raw by av_kernel)
    #pragma unroll
    for (int ni = 0; ni < 2; ++ni)
        #pragma unroll
        for (int t = 0; t < sf[ni].num_elements; ++t)
            sf[ni].x[t] = wmma::__float_to_tf32(__expf(sf[ni].x[t] * 0.125f));

    __syncthreads();   // all warps done reading KR; safe to reuse KR[0] as P staging
    float (*Ps)[68] = reinterpret_cast<float (*)[68]>(&sm->KR[0][0][0]);
    #pragma unroll
    for (int ni = 0; ni < 2; ++ni)
        wmma::store_matrix_sync(&Ps[wb*16][wn*32 + ni*16], sf[ni], 68,
                                wmma::mem_row_major);
    __syncthreads();

    // Writeout + row-sum atomics: 4 threads per row (16-col quarters)
    {
        int r = tid >> 2;           // 0..63   (b,h)
        int q = tid & 3;
        int b = r >> 4, h = r & 15;
        size_t grow = ((size_t)(b*SEQ + i))*16 + h;
        float* dst = g_p + grow*SEQ + j0 + q*16;
        float s = 0.0f;
        #pragma unroll
        for (int c = 0; c < 4; ++c) {
            float4 v = *reinterpret_cast<float4*>(&Ps[r][q*16 + c*4]);
            s += v.x + v.y + v.z + v.w;
            *reinterpret_cast<float4*>(dst + c*4) = v;
        }
        s += __shfl_xor_sync(0xffffffffu, s, 1);
        s += __shfl_xor_sync(0xffffffffu, s, 2);
        if (q == 0) atomicAdd(&g_l[grow], s);
    }
}

// ===========================================================================
// AV: ctx[b,(i,h),d] = (P_b[(i,h),:] · V_b) / l.  Per-b GEMM M=16384,N=64,K=1024
// cp.async double-buffered.  P and V are pre-rounded tf32 — zero cvts.
// ===========================================================================
struct AvSmem { float A[2][128][36]; float B[2][32][68]; };
#define AV_SMEM ((int)sizeof(AvSmem))

__global__ void __launch_bounds__(256, 2)
av_kernel()
{
    extern __shared__ float smraw[];
    AvSmem* sm = reinterpret_cast<AvSmem*>(smraw);

    const int tid  = threadIdx.x;
    const int warp = tid >> 5;
    const int wm   = warp >> 1;        // 0..3
    const int wn   = warp & 1;         // 0..1
    const int b    = blockIdx.y;
    const size_t m0 = (size_t)blockIdx.x * 128;

    const float* Pb = g_p + (size_t)b*SEQ*16*SEQ + m0*SEQ;
    const float* Vb = g_v + (size_t)b*SEQ*DH;
    float*       Cb = g_ctx + ((size_t)b*SEQ*16 + m0)*DH;

    auto stage = [&](int buf, int k0) {
        #pragma unroll
        for (int t = 0; t < 4; ++t) {
            int idx = tid + t*256;          // 0..1023
            int r   = idx >> 3;             // 0..127
            int c4  = (idx & 7) * 4;
            cp16(&sm->A[buf][r][c4], Pb + (size_t)r*SEQ + k0 + c4);
        }
        #pragma unroll
        for (int t = 0; t < 2; ++t) {
            int idx = tid + t*256;          // 0..511
            int r   = idx >> 4;             // 0..31
            int c4  = (idx & 15) * 4;
            cp16(&sm->B[buf][r][c4], Vb + (size_t)(k0 + r)*DH + c4);
        }
        cp_commit();
    };

    wmma::fragment<wmma::accumulator, 16, 16, 8, float> of[2][2];
    #pragma unroll
    for (int mi = 0; mi < 2; ++mi)
        #pragma unroll
        for (int ni = 0; ni < 2; ++ni) wmma::fill_fragment(of[mi][ni], 0.0f);

    stage(0, 0);
    int cur = 0;
    for (int k0 = 0; k0 < SEQ; k0 += 32) {
        if (k0 + 32 < SEQ) { stage(cur ^ 1, k0 + 32); cp_wait<1>(); }
        else               { cp_wait<0>(); }
        __syncthreads();

        #pragma unroll
        for (int kf = 0; kf < 4; ++kf) {
            wmma::fragment<wmma::matrix_a, 16, 16, 8, wmma::precision::tf32, wmma::row_major> af[2];
            wmma::fragment<wmma::matrix_b, 16, 16, 8, wmma::precision::tf32, wmma::row_major> bf[2];
            #pragma unroll
            for (int mi = 0; mi < 2; ++mi)
                wmma::load_matrix_sync(af[mi], &sm->A[cur][wm*32 + mi*16][kf*8], 36);
            #pragma unroll
            for (int ni = 0; ni < 2; ++ni)
                wmma::load_matrix_sync(bf[ni], &sm->B[cur][kf*8][wn*32 + ni*16], 68);
            #pragma unroll
            for (int mi = 0; mi < 2; ++mi)
                #pragma unroll
                for (int ni = 0; ni < 2; ++ni)
                    wmma::mma_sync(of[mi][ni], af[mi], bf[ni], of[mi][ni]);
        }
        __syncthreads();
        cur ^= 1;
    }

    // Epilogue: stage O through smem (alias over A buffers), divide by l
    float (*Cs)[68] = reinterpret_cast<float (*)[68]>(&sm->A[0][0][0]);
    #pragma unroll
    for (int mi = 0; mi < 2; ++mi)
        #pragma unroll
        for (int ni = 0; ni < 2; ++ni)
            wmma::store_matrix_sync(&Cs[wm*32 + mi*16][wn*32 + ni*16],
                                    of[mi][ni], 68, wmma::mem_row_major);
    __syncthreads();

    {
        int r    = tid >> 1;       // 0..127
        int half = tid & 1;
        float inv = 1.0f / g_l[(size_t)b*SEQ*16 + m0 + r];
        #pragma unroll
        for (int c = 0; c < 8; ++c) {
            float4 v = *reinterpret_cast<float4*>(&Cs[r][half*32 + c*4]);
            v.x *= inv; v.y *= inv; v.z *= inv; v.w *= inv;
            *reinterpret_cast<float4*>(Cb + (size_t)r*DH + half*32 + c*4) = v;
        }
    }
}

// ===========================================================================
// 128x128 NT GEMM (C = A·B^T), cp.async double-buffered, 8 warps (warp 32x64)
// Per-fragment tf32 convert (R8-proven).  round_out=1 rounds C to tf32.
// ===========================================================================
struct ProjSmem { float A[2][128][36]; float B[2][128][36]; };
#define PROJ_SMEM ((int)sizeof(ProjSmem))

__global__ void __launch_bounds__(256, 2)
gemm_nt_128p(const float* __restrict__ A, int lda,
             const float* __restrict__ B, int ldb,
             float* __restrict__ C, int ldc, int K, int round_out)
{
    extern __shared__ float smraw[];
    ProjSmem* sm = reinterpret_cast<ProjSmem*>(smraw);

    const int tid  = threadIdx.x;
    const int warp = tid >> 5;
    const int wm   = warp >> 1;      // 0..3
    const int wn   = warp & 1;       // 0..1

    A += (size_t)blockIdx.x * 128 * lda;
    B += (size_t)blockIdx.y * 128 * ldb;
    C += (size_t)blockIdx.x * 128 * ldc + (size_t)blockIdx.y * 128;

    auto stage = [&](int buf, int k0) {
        #pragma unroll
        for (int t = 0; t < 4; ++t) {
            int idx = tid + t*256;           // 0..1023
            int r   = idx >> 3;              // 0..127
            int c4  = (idx & 7) * 4;         // 0..28
            cp16(&sm->A[buf][r][c4], A + (size_t)r*lda + k0 + c4);
            cp16(&sm->B[buf][r][c4], B + (size_t)r*ldb + k0 + c4);
        }
        cp_commit();
    };

    wmma::fragment<wmma::accumulator, 16, 16, 8, float> cf[2][4];
    #pragma unroll
    for (int mi = 0; mi < 2; ++mi)
        #pragma unroll
        for (int ni = 0; ni < 4; ++ni) wmma::fill_fragment(cf[mi][ni], 0.0f);

    stage(0, 0);
    int cur = 0;
    for (int k0 = 0; k0 < K; k0 += 32) {
        if (k0 + 32 < K) { stage(cur ^ 1, k0 + 32); cp_wait<1>(); }
        else             { cp_wait<0>(); }
        __syncthreads();

        #pragma unroll
        for (int kf = 0; kf < 4; ++kf) {
            wmma::fragment<wmma::matrix_a, 16, 16, 8, wmma::precision::tf32, wmma::row_major> af[2];
            wmma::fragment<wmma::matrix_b, 16, 16, 8, wmma::precision::tf32, wmma::col_major> bf[4];
            #pragma unroll
            for (int mi = 0; mi < 2; ++mi) {
                wmma::load_matrix_sync(af[mi], &sm->A[cur][wm*32 + mi*16][kf*8], 36);
                to_tf32(af[mi]);
            }
            #pragma unroll
            for (int ni = 0; ni < 4; ++ni) {
                wmma::load_matrix_sync(bf[ni], &sm->B[cur][wn*64 + ni*16][kf*8], 36);
                to_tf32(bf[ni]);
            }
            #pragma unroll
            for (int mi = 0; mi < 2; ++mi)
                #pragma unroll
                for (int ni = 0; ni < 4; ++ni)
                    wmma::mma_sync(cf[mi][ni], af[mi], bf[ni], cf[mi][ni]);
        }
        __syncthreads();
        cur ^= 1;
    }

    if (round_out) {
        #pragma unroll
        for (int mi = 0; mi < 2; ++mi)
            #pragma unroll
            for (int ni = 0; ni < 4; ++ni) to_tf32(cf[mi][ni]);
    }
    #pragma unroll
    for (int mi = 0; mi < 2; ++mi)
        #pragma unroll
        for (int ni = 0; ni < 4; ++ni)
            wmma::store_matrix_sync(
                C + (size_t)(wm*32 + mi*16)*ldc + (wn*64 + ni*16),
                cf[mi][ni], ldc, wmma::mem_row_major);
}

// ===========================================================================
// Combined K/V projection: one 128-wide NT GEMM over stacked [Wk; Wv].
// x read once.  Outputs tf32-rounded into g_k / g_v.
// ===========================================================================
__global__ void __launch_bounds__(256, 2)
kv_proj_kernel(const float* __restrict__ x,
               const float* __restrict__ Wk,
               const float* __restrict__ Wv)
{
    extern __shared__ float smraw[];
    ProjSmem* sm = reinterpret_cast<ProjSmem*>(smraw);

    const int tid  = threadIdx.x;
    const int warp = tid >> 5;
    const int wm   = warp >> 1;      // 0..3
    const int wn   = warp & 1;       // 0 -> K, 1 -> V

    const float* Ax = x + (size_t)blockIdx.x * 128 * DMODEL;

    auto stage = [&](int buf, int k0) {
        #pragma unroll
        for (int t = 0; t < 4; ++t) {
            int idx = tid + t*256;
            int r   = idx >> 3;
            int c4  = (idx & 7) * 4;
            cp16(&sm->A[buf][r][c4], Ax + (size_t)r*DMODEL + k0 + c4);
            const float* src = (r < 64) ? (Wk + (size_t)r*DMODEL)
                                        : (Wv + (size_t)(r - 64)*DMODEL);
            cp16(&sm->B[buf][r][c4], src + k0 + c4);
        }
        cp_commit();
    };

    wmma::fragment<wmma::accumulator, 16, 16, 8, float> cf[2][4];
    #pragma unroll
    for (int mi = 0; mi < 2; ++mi)
        #pragma unroll
        for (int ni = 0; ni < 4; ++ni) wmma::fill_fragment(cf[mi][ni], 0.0f);

    stage(0, 0);
    int cur = 0;
    for (int k0 = 0; k0 < DMODEL; k0 += 32) {
        if (k0 + 32 < DMODEL) { stage(cur ^ 1, k0 + 32); cp_wait<1>(); }
        else                  { cp_wait<0>(); }
        __syncthreads();

        #pragma unroll
        for (int kf = 0; kf < 4; ++kf) {
            wmma::fragment<wmma::matrix_a, 16, 16, 8, wmma::precision::tf32, wmma::row_major> af[2];
            wmma::fragment<wmma::matrix_b, 16, 16, 8, wmma::precision::tf32, wmma::col_major> bf[4];
            #pragma unroll
            for (int mi = 0; mi < 2; ++mi) {
                wmma::load_matrix_sync(af[mi], &sm->A[cur][wm*32 + mi*16][kf*8], 36);
                to_tf32(af[mi]);
            }
            #pragma unroll
            for (int ni = 0; ni < 4; ++ni) {
                wmma::load_matrix_sync(bf[ni], &sm->B[cur][wn*64 + ni*16][kf*8], 36);
                to_tf32(bf[ni]);
            }
            #pragma unroll
            for (int mi = 0; mi < 2; ++mi)
                #pragma unroll
                for (int ni = 0; ni < 4; ++ni)
                    wmma::mma_sync(cf[mi][ni], af[mi], bf[ni], cf[mi][ni]);
        }
        __syncthreads();
        cur ^= 1;
    }

    #pragma unroll
    for (int mi = 0; mi < 2; ++mi)
        #pragma unroll
        for (int ni = 0; ni < 4; ++ni) to_tf32(cf[mi][ni]);

    float* Ct = (wn == 0) ? g_k : g_v;
    Ct += ((size_t)blockIdx.x * 128 + wm*32) * DH;
    #pragma unroll
    for (int mi = 0; mi < 2; ++mi)
        #pragma unroll
        for (int ni = 0; ni < 4; ++ni)
            wmma::store_matrix_sync(
                Ct + (size_t)(mi*16)*DH + ni*16,
                cf[mi][ni], DH, wmma::mem_row_major);
}

// ---------------------------------------------------------------------------
__global__ void bias_add(float* __restrict__ out, const float* __restrict__ bo)
{
    size_t idx = (size_t)blockIdx.x * 256 + threadIdx.x;
    out[idx] += bo[idx & (DMODEL - 1)];
}

// ---------------------------------------------------------------------------
extern "C" void kernel_launch(void* const* d_in, const int* in_sizes, int n_in,
                              void* d_out, int out_size)
{
    const float* x   = (const float*)d_in[0];
    const float* rel = (const float*)d_in[1];
    const float* Wq  = (const float*)d_in[2];
    const float* Wk  = (const float*)d_in[3];
    const float* Wv  = (const float*)d_in[4];
    const float* Wo  = (const float*)d_in[5];
    const float* bo  = (const float*)d_in[6];
    float* out = (float*)d_out;

    float *q, *l, *ctx;
    cudaGetSymbolAddress((void**)&q,   g_q);
    cudaGetSymbolAddress((void**)&l,   g_l);
    cudaGetSymbolAddress((void**)&ctx, g_ctx);

    cudaFuncSetAttribute(gemm_nt_128p,  cudaFuncAttributeMaxDynamicSharedMemorySize, PROJ_SMEM);
    cudaFuncSetAttribute(kv_proj_kernel, cudaFuncAttributeMaxDynamicSharedMemorySize, PROJ_SMEM);
    cudaFuncSetAttribute(c2cp_kernel,   cudaFuncAttributeMaxDynamicSharedMemorySize, C2P_SMEM);
    cudaFuncSetAttribute(av_kernel,     cudaFuncAttributeMaxDynamicSharedMemorySize, AV_SMEM);

    // Projections: y = x @ W^T  (Q/K/V outputs tf32-rounded at source)
    gemm_nt_128p<<<dim3(32, 8), 256, PROJ_SMEM>>>(x, DMODEL, Wq, DMODEL, q, DMODEL, DMODEL, 1);
    kv_proj_kernel<<<32, 256, PROJ_SMEM>>>(x, Wk, Wv);

    // Zero row-sum accumulators
    cudaMemsetAsync(l, 0, (size_t)BATCH*SEQ*NH*sizeof(float));

    // P = exp(q·(k+rel)/8), row sums via atomics
    c2cp_kernel<<<dim3(SEQ, SEQ/JC2), 256, C2P_SMEM>>>(rel);

    // ctx = (P · V) / l
    av_kernel<<<dim3(128, BATCH), 256, AV_SMEM>>>();

    // out = ctx @ Wo^T + bo
    gemm_nt_128p<<<dim3(32, 8), 256, PROJ_SMEM>>>(ctx, DMODEL, Wo, DMODEL, out, DMODEL, DMODEL, 0);
    bias_add<<<16384, 256>>>(out, bo);
}